// round 1
// baseline (speedup 1.0000x reference)
#include <cuda_runtime.h>
#include <math.h>

#define BB   131072
#define TT   30
#define HH   150
#define GG   450      // 3*H
#define SDD  50
#define TB   32       // batch tile per CTA
#define NTH  256

// Device scratch for transposed weights (allowed: __device__ globals).
__device__ float g_WhhT[HH * GG];        // [k][j], k<150, j<450
__device__ float g_WihT[TT * 2 * GG];    // [c][j], c<60, j<450

// ---------- packed fp32x2 FMA (sm_103a) ----------
__device__ __forceinline__ float2 ffma2(float2 a, float2 b, float2 c) {
    float2 r;
    asm("{\n\t"
        ".reg .b64 ra, rb, rc, rd;\n\t"
        "mov.b64 ra, {%2, %3};\n\t"
        "mov.b64 rb, {%4, %5};\n\t"
        "mov.b64 rc, {%6, %7};\n\t"
        "fma.rn.f32x2 rd, ra, rb, rc;\n\t"
        "mov.b64 {%0, %1}, rd;\n\t"
        "}"
        : "=f"(r.x), "=f"(r.y)
        : "f"(a.x), "f"(a.y), "f"(b.x), "f"(b.y), "f"(c.x), "f"(c.y));
    return r;
}

__device__ __forceinline__ float sigmf(float v) {
    return 1.0f / (1.0f + expf(-v));
}
__device__ __forceinline__ float softplusf(float v) {
    return fmaxf(v, 0.0f) + log1pf(expf(-fabsf(v)));
}

// gh stored with pair-swizzle to avoid STS bank conflicts:
// writer (row j, batch-pair p) stores float2 at pair-slot (p+j)&15
__device__ __forceinline__ int gh_idx(int j, int b) {
    return j * TB + ((((b >> 1) + j) & 15) << 1) + (b & 1);
}

// ---------- setup: transpose W_hh and W_ih ----------
__global__ void transpose_weights(const float* __restrict__ Whh,
                                  const float* __restrict__ Wih) {
    int idx = blockIdx.x * blockDim.x + threadIdx.x;
    if (idx < GG * HH) {            // Whh[j][k] -> WhhT[k][j]
        int j = idx / HH, k = idx % HH;
        g_WhhT[k * GG + j] = Whh[idx];
    }
    if (idx < GG * (TT * 2)) {      // Wih[j][c] -> WihT[c][j]
        int j = idx / (TT * 2), c = idx % (TT * 2);
        g_WihT[c * GG + j] = Wih[idx];
    }
}

// ---------- main fused recurrent kernel ----------
extern "C" __global__ void __launch_bounds__(NTH, 1)
r2p2_kernel(const float* __restrict__ stat,
            const float* __restrict__ init_v,
            const float* __restrict__ init_p,
            const float* __restrict__ zin,
            const float* __restrict__ b_ih,
            const float* __restrict__ b_hh,
            const float* __restrict__ W1,
            const float* __restrict__ b1,
            const float* __restrict__ W2,
            const float* __restrict__ b2,
            float* __restrict__ out) {
    extern __shared__ float smem[];
    float* s_gi = smem;                    // GG*TB   (layout [j][b])
    float* s_gh = s_gi + GG * TB;          // GG*TB   (swizzled)
    float* s_h  = s_gh + GG * TB;          // HH*TB   (layout [k][b])
    float* s_sp = s_h  + HH * TB;          // SDD*TB  (static proj + b1)
    float* s_o1 = s_sp + SDD * TB;         // SDD*TB
    float* s_x  = s_o1 + SDD * TB;         // TB*2

    const int tid = threadIdx.x;
    const int b0  = blockIdx.x * TB;

    // ---- init: h = 0, gi = b_ih, s_proj = b1 + static @ W1_static^T ----
    for (int idx = tid; idx < HH * TB; idx += NTH) s_h[idx] = 0.0f;
    for (int idx = tid; idx < GG * TB; idx += NTH) s_gi[idx] = b_ih[idx >> 5];
    for (int idx = tid; idx < SDD * TB; idx += NTH) {
        int m = idx >> 5, b = idx & 31;
        float acc = b1[m];
        const float* wrow = W1 + m * (HH + SDD) + HH;
        const float* st   = stat + (size_t)(b0 + b) * SDD;
        #pragma unroll 5
        for (int d = 0; d < SDD; ++d) acc = fmaf(wrow[d], st[d], acc);
        s_sp[idx] = acc;
    }

    float xp0 = 0.f, xp1 = 0.f, dx0 = 0.f, dx1 = 0.f;
    if (tid < TB) {
        size_t g = (size_t)(b0 + tid) * 2;
        xp0 = init_p[g]; xp1 = init_p[g + 1];
        dx0 = init_v[g]; dx1 = init_v[g + 1];
    }
    __syncthreads();

    const size_t SIG_OFF = (size_t)2 * TT * BB;
    const size_t X_OFF   = (size_t)6 * TT * BB;

    for (int t = 0; t < TT; ++t) {
        // ===== Phase A: gh = h @ W_hh^T + b_hh  (rows j0=tid, j1=tid+256) =====
        {
            float2 accA[16], accB[16];
            #pragma unroll
            for (int p = 0; p < 16; ++p) {
                accA[p] = make_float2(0.f, 0.f);
                accB[p] = make_float2(0.f, 0.f);
            }
            const int j0 = tid, j1 = tid + NTH;
            const bool hasB = (j1 < GG);
            #pragma unroll 2
            for (int k = 0; k < HH; ++k) {
                float wa = g_WhhT[k * GG + j0];
                float wb = hasB ? g_WhhT[k * GG + j1] : 0.0f;
                float2 wa2 = make_float2(wa, wa);
                float2 wb2 = make_float2(wb, wb);
                const float2* hp = reinterpret_cast<const float2*>(s_h) + k * 16;
                #pragma unroll
                for (int p = 0; p < 16; ++p) {
                    float2 hv = hp[p];
                    accA[p] = ffma2(hv, wa2, accA[p]);
                    accB[p] = ffma2(hv, wb2, accB[p]);
                }
            }
            float bhA = b_hh[j0];
            float2* rowA = reinterpret_cast<float2*>(s_gh + j0 * TB);
            #pragma unroll
            for (int p = 0; p < 16; ++p) {
                float2 v = accA[p]; v.x += bhA; v.y += bhA;
                rowA[(p + j0) & 15] = v;
            }
            if (hasB) {
                float bhB = b_hh[j1];
                float2* rowB = reinterpret_cast<float2*>(s_gh + j1 * TB);
                #pragma unroll
                for (int p = 0; p < 16; ++p) {
                    float2 v = accB[p]; v.x += bhB; v.y += bhB;
                    rowB[(p + j1) & 15] = v;
                }
            }
        }
        __syncthreads();

        // ===== Phase B: GRU gates, h update (in place) =====
        for (int idx = tid; idx < HH * TB; idx += NTH) {
            int j = idx >> 5, b = idx & 31;
            float ir  = s_gi[j * TB + b];
            float iz  = s_gi[(j + HH) * TB + b];
            float inn = s_gi[(j + 2 * HH) * TB + b];
            float hr  = s_gh[gh_idx(j, b)];
            float hz  = s_gh[gh_idx(j + HH, b)];
            float hn  = s_gh[gh_idx(j + 2 * HH, b)];
            float r  = sigmf(ir + hr);
            float zg = sigmf(iz + hz);
            float n  = tanhf(fmaf(r, hn, inn));
            float hold = s_h[idx];
            s_h[idx] = fmaf(zg, hold - n, n);   // (1-zg)*n + zg*h
        }
        __syncthreads();

        // ===== Phase C: o1 = softplus(h_new @ W1h^T + s_proj) =====
        for (int idx = tid; idx < SDD * 16; idx += NTH) {
            int m = idx >> 4, bp = idx & 15;
            float2 acc = make_float2(0.f, 0.f);
            const float* wrow = W1 + m * (HH + SDD);
            const float2* hcol = reinterpret_cast<const float2*>(s_h) + bp;
            #pragma unroll 5
            for (int k = 0; k < HH; ++k) {
                float w = wrow[k];
                acc = ffma2(hcol[k * 16], make_float2(w, w), acc);
            }
            float2 sp = reinterpret_cast<const float2*>(s_sp)[m * 16 + bp];
            s_o1[m * TB + 2 * bp]     = softplusf(acc.x + sp.x);
            s_o1[m * TB + 2 * bp + 1] = softplusf(acc.y + sp.y);
        }
        __syncthreads();

        // ===== Phase D: o2, expm 2x2, x update, outputs (one thread per b) =====
        if (tid < TB) {
            const int b = tid;
            const int gb = b0 + b;
            float o2[6];
            #pragma unroll
            for (int p = 0; p < 6; ++p) {
                float acc = b2[p];
                const float* w = W2 + p * SDD;
                #pragma unroll 5
                for (int m = 0; m < SDD; ++m)
                    acc = fmaf(w[m], s_o1[m * TB + b], acc);
                o2[p] = softplusf(acc);
            }
            float aS = 2.0f * o2[2];
            float bS = o2[3] + o2[4];
            float cS = 2.0f * o2[5];
            float half_tr   = 0.5f * (aS + cS);
            float half_diff = 0.5f * (aS - cS);
            float disc = sqrtf(fmaf(half_diff, half_diff, bS * bS));
            float d = fmaxf(disc, 1e-12f);
            float sinhc = sinhf(d) / d;
            float coshd = coshf(disc);
            float scale = expf(half_tr);
            float m00 = scale * fmaf(sinhc,  half_diff, coshd);
            float m11 = scale * fmaf(-sinhc, half_diff, coshd);
            float m01 = scale * (sinhc * bS);

            float mu0 = xp0 + dx0 + o2[0];
            float mu1 = xp1 + dx1 + o2[1];
            float2 zv = reinterpret_cast<const float2*>(zin)[(size_t)t * BB + gb];
            float x0 = fmaf(m00, zv.x, fmaf(m01, zv.y, mu0));
            float x1 = fmaf(m01, zv.x, fmaf(m11, zv.y, mu1));
            dx0 = x0 - xp0; dx1 = x1 - xp1;
            xp0 = x0;       xp1 = x1;

            reinterpret_cast<float2*>(out)[(size_t)t * BB + gb] = make_float2(mu0, mu1);
            reinterpret_cast<float4*>(out + SIG_OFF)[(size_t)t * BB + gb] =
                make_float4(m00, m01, m01, m11);
            reinterpret_cast<float2*>(out + X_OFF)[(size_t)t * BB + gb] = make_float2(x0, x1);
            s_x[2 * b]     = x0;
            s_x[2 * b + 1] = x1;
        }
        __syncthreads();

        // ===== Phase E: gi += W_ih[:,2t]*x0 + W_ih[:,2t+1]*x1 (rank-2 update) =====
        if (t < TT - 1) {
            const int c0 = 2 * t;
            for (int idx = tid; idx < GG * 16; idx += NTH) {
                int j = idx >> 4, bp = idx & 15;
                float w0 = g_WihT[c0 * GG + j];
                float w1 = g_WihT[(c0 + 1) * GG + j];
                float2 xb0 = make_float2(s_x[4 * bp],     s_x[4 * bp + 2]);
                float2 xb1 = make_float2(s_x[4 * bp + 1], s_x[4 * bp + 3]);
                float2 g = reinterpret_cast<float2*>(s_gi)[j * 16 + bp];
                g = ffma2(xb0, make_float2(w0, w0), g);
                g = ffma2(xb1, make_float2(w1, w1), g);
                reinterpret_cast<float2*>(s_gi)[j * 16 + bp] = g;
            }
        }
        __syncthreads();
    }
}

extern "C" void kernel_launch(void* const* d_in, const int* in_sizes, int n_in,
                              void* d_out, int out_size) {
    const float* stat   = (const float*)d_in[0];
    const float* init_v = (const float*)d_in[1];
    const float* init_p = (const float*)d_in[2];
    const float* z      = (const float*)d_in[3];
    const float* W_ih   = (const float*)d_in[4];
    const float* W_hh   = (const float*)d_in[5];
    const float* b_ih   = (const float*)d_in[6];
    const float* b_hh   = (const float*)d_in[7];
    const float* W1     = (const float*)d_in[8];
    const float* b1     = (const float*)d_in[9];
    const float* W2     = (const float*)d_in[10];
    const float* b2     = (const float*)d_in[11];
    float* out = (float*)d_out;

    transpose_weights<<<(GG * HH + 255) / 256, 256>>>(W_hh, W_ih);

    const size_t smem_bytes =
        (size_t)(GG * TB * 2 + HH * TB + SDD * TB * 2 + TB * 2) * sizeof(float);
    cudaFuncSetAttribute(r2p2_kernel,
                         cudaFuncAttributeMaxDynamicSharedMemorySize,
                         (int)smem_bytes);
    r2p2_kernel<<<BB / TB, NTH, smem_bytes>>>(
        stat, init_v, init_p, z, b_ih, b_hh, W1, b1, W2, b2, out);
}

// round 2
// speedup vs baseline: 1.9331x; 1.9331x over previous
#include <cuda_runtime.h>
#include <math.h>

#define BB   131072
#define TT   30
#define HH   150
#define GG   450      // 3*H
#define SDD  50
#define TB   32       // batch tile per CTA
#define NTH  320      // 10 warps; 300 active in GEMM phase

// Device scratch for transposed weights (allowed: __device__ globals).
__device__ float g_WhhT[HH * GG];        // [k][j], k<150, j<450
__device__ float g_WihT[TT * 2 * GG];    // [c][j], c<60, j<450

// ---------- packed fp32x2 FMA (sm_103a) ----------
__device__ __forceinline__ float2 ffma2(float2 a, float2 b, float2 c) {
    float2 r;
    asm("{\n\t"
        ".reg .b64 ra, rb, rc, rd;\n\t"
        "mov.b64 ra, {%2, %3};\n\t"
        "mov.b64 rb, {%4, %5};\n\t"
        "mov.b64 rc, {%6, %7};\n\t"
        "fma.rn.f32x2 rd, ra, rb, rc;\n\t"
        "mov.b64 {%0, %1}, rd;\n\t"
        "}"
        : "=f"(r.x), "=f"(r.y)
        : "f"(a.x), "f"(a.y), "f"(b.x), "f"(b.y), "f"(c.x), "f"(c.y));
    return r;
}

__device__ __forceinline__ float sigmf(float v) {
    return 1.0f / (1.0f + expf(-v));
}
__device__ __forceinline__ float softplusf(float v) {
    return fmaxf(v, 0.0f) + log1pf(expf(-fabsf(v)));
}

// ---------- setup: transpose W_hh and W_ih ----------
__global__ void transpose_weights(const float* __restrict__ Whh,
                                  const float* __restrict__ Wih) {
    int idx = blockIdx.x * blockDim.x + threadIdx.x;
    if (idx < GG * HH) {            // Whh[j][k] -> WhhT[k][j]
        int j = idx / HH, k = idx % HH;
        g_WhhT[k * GG + j] = Whh[idx];
    }
    if (idx < GG * (TT * 2)) {      // Wih[j][c] -> WihT[c][j]
        int j = idx / (TT * 2), c = idx % (TT * 2);
        g_WihT[c * GG + j] = Wih[idx];
    }
}

// ---------- main fused recurrent kernel ----------
extern "C" __global__ void __launch_bounds__(NTH, 2)
r2p2_kernel(const float* __restrict__ stat,
            const float* __restrict__ init_v,
            const float* __restrict__ init_p,
            const float* __restrict__ zin,
            const float* __restrict__ b_ih,
            const float* __restrict__ b_hh,
            const float* __restrict__ W1,
            const float* __restrict__ b1,
            const float* __restrict__ W2,
            const float* __restrict__ b2,
            float* __restrict__ out) {
    extern __shared__ float smem[];
    float* s_gi = smem;                    // GG*TB   (layout [j][b])
    float* s_h  = s_gi + GG * TB;          // HH*TB   (layout [k][b])
    float* s_sp = s_h  + HH * TB;          // SDD*TB  (static proj + b1)
    float* s_o1 = s_sp + SDD * TB;         // SDD*TB
    float* s_o2 = s_o1 + SDD * TB;         // 6*TB
    float* s_x  = s_o2 + 6 * TB;           // TB*2

    const int tid = threadIdx.x;
    const int b0  = blockIdx.x * TB;
    const bool actA = (tid < 300);
    const int j    = tid >> 1;     // hidden unit 0..149
    const int half = tid & 1;      // batch-pair half: pairs [half*8, half*8+8)

    // ---- init: h = 0, gi = b_ih, s_proj = b1 + static @ W1_static^T ----
    for (int idx = tid; idx < HH * TB; idx += NTH) s_h[idx] = 0.0f;
    for (int idx = tid; idx < GG * TB; idx += NTH) s_gi[idx] = b_ih[idx >> 5];
    for (int idx = tid; idx < SDD * TB; idx += NTH) {
        int m = idx >> 5, b = idx & 31;
        float acc = b1[m];
        const float* wrow = W1 + m * (HH + SDD) + HH;
        const float* st   = stat + (size_t)(b0 + b) * SDD;
        #pragma unroll 5
        for (int d = 0; d < SDD; ++d) acc = fmaf(wrow[d], st[d], acc);
        s_sp[idx] = acc;
    }

    float xp0 = 0.f, xp1 = 0.f, dx0 = 0.f, dx1 = 0.f;
    if (tid < TB) {
        size_t g = (size_t)(b0 + tid) * 2;
        xp0 = init_p[g]; xp1 = init_p[g + 1];
        dx0 = init_v[g]; dx1 = init_v[g + 1];
    }
    __syncthreads();

    const size_t SIG_OFF = (size_t)2 * TT * BB;
    const size_t X_OFF   = (size_t)6 * TT * BB;

    for (int t = 0; t < TT; ++t) {
        // ===== Phase A: per-thread 3-gate rows (j, j+150, j+300) x 8 pairs =====
        float2 accR[8], accZ[8], accN[8];
        if (actA) {
            #pragma unroll
            for (int p = 0; p < 8; ++p) {
                accR[p] = make_float2(0.f, 0.f);
                accZ[p] = make_float2(0.f, 0.f);
                accN[p] = make_float2(0.f, 0.f);
            }
            const float* wp = g_WhhT + j;
            const float2* hp = reinterpret_cast<const float2*>(s_h) + half * 8;
            #pragma unroll 2
            for (int k = 0; k < HH; ++k) {
                float wr = __ldg(wp);
                float wz = __ldg(wp + HH);
                float wn = __ldg(wp + 2 * HH);
                wp += GG;
                float2 wr2 = make_float2(wr, wr);
                float2 wz2 = make_float2(wz, wz);
                float2 wn2 = make_float2(wn, wn);
                #pragma unroll
                for (int p = 0; p < 8; ++p) {
                    float2 hv = hp[p];
                    accR[p] = ffma2(hv, wr2, accR[p]);
                    accZ[p] = ffma2(hv, wz2, accZ[p]);
                    accN[p] = ffma2(hv, wn2, accN[p]);
                }
                hp += 16;
            }
        }
        __syncthreads();   // all reads of old h complete

        // ===== Phase B: GRU gates in-register, write h_new =====
        if (actA) {
            float bhr = b_hh[j];
            float bhz = b_hh[j + HH];
            float bhn = b_hh[j + 2 * HH];
            const float2* gi2 = reinterpret_cast<const float2*>(s_gi);
            float2* h2 = reinterpret_cast<float2*>(s_h);
            #pragma unroll
            for (int p = 0; p < 8; ++p) {
                int pr = half * 8 + p;
                float2 vr = gi2[j * 16 + pr];
                float2 vz = gi2[(j + HH) * 16 + pr];
                float2 vn = gi2[(j + 2 * HH) * 16 + pr];
                float rx = sigmf(vr.x + accR[p].x + bhr);
                float ry = sigmf(vr.y + accR[p].y + bhr);
                float zx = sigmf(vz.x + accZ[p].x + bhz);
                float zy = sigmf(vz.y + accZ[p].y + bhz);
                float nx = tanhf(fmaf(rx, accN[p].x + bhn, vn.x));
                float ny = tanhf(fmaf(ry, accN[p].y + bhn, vn.y));
                float2 hold = h2[j * 16 + pr];
                float2 hnew;
                hnew.x = fmaf(zx, hold.x - nx, nx);
                hnew.y = fmaf(zy, hold.y - ny, ny);
                h2[j * 16 + pr] = hnew;
            }
        }
        __syncthreads();

        // ===== Phase C: o1 = softplus(h_new @ W1h^T + s_proj) =====
        for (int idx = tid; idx < SDD * 16; idx += NTH) {
            int m = idx >> 4, bp = idx & 15;
            float2 acc = make_float2(0.f, 0.f);
            const float* wrow = W1 + m * (HH + SDD);
            const float2* hcol = reinterpret_cast<const float2*>(s_h) + bp;
            #pragma unroll 5
            for (int k = 0; k < HH; ++k) {
                float w = wrow[k];
                acc = ffma2(hcol[k * 16], make_float2(w, w), acc);
            }
            float2 sp = reinterpret_cast<const float2*>(s_sp)[m * 16 + bp];
            s_o1[m * TB + 2 * bp]     = softplusf(acc.x + sp.x);
            s_o1[m * TB + 2 * bp + 1] = softplusf(acc.y + sp.y);
        }
        __syncthreads();

        // ===== Phase D1: o2 = softplus(o1 @ W2^T + b2), 192 threads =====
        if (tid < 192) {
            int m = tid >> 5, b = tid & 31;
            float acc = b2[m];
            const float* w = W2 + m * SDD;
            #pragma unroll 5
            for (int k = 0; k < SDD; ++k)
                acc = fmaf(w[k], s_o1[k * TB + b], acc);
            s_o2[m * TB + b] = softplusf(acc);
        }
        __syncthreads();

        // ===== Phase D2: expm 2x2, x update, outputs (one thread per b) =====
        if (tid < TB) {
            const int b = tid;
            const int gb = b0 + b;
            float o20 = s_o2[0 * TB + b];
            float o21 = s_o2[1 * TB + b];
            float aS = 2.0f * s_o2[2 * TB + b];
            float bS = s_o2[3 * TB + b] + s_o2[4 * TB + b];
            float cS = 2.0f * s_o2[5 * TB + b];
            float half_tr   = 0.5f * (aS + cS);
            float half_diff = 0.5f * (aS - cS);
            float disc = sqrtf(fmaf(half_diff, half_diff, bS * bS));
            float d = fmaxf(disc, 1e-12f);
            float sinhc = sinhf(d) / d;
            float coshd = coshf(disc);
            float scale = expf(half_tr);
            float m00 = scale * fmaf(sinhc,  half_diff, coshd);
            float m11 = scale * fmaf(-sinhc, half_diff, coshd);
            float m01 = scale * (sinhc * bS);

            float mu0 = xp0 + dx0 + o20;
            float mu1 = xp1 + dx1 + o21;
            float2 zv = reinterpret_cast<const float2*>(zin)[(size_t)t * BB + gb];
            float x0 = fmaf(m00, zv.x, fmaf(m01, zv.y, mu0));
            float x1 = fmaf(m01, zv.x, fmaf(m11, zv.y, mu1));
            dx0 = x0 - xp0; dx1 = x1 - xp1;
            xp0 = x0;       xp1 = x1;

            reinterpret_cast<float2*>(out)[(size_t)t * BB + gb] = make_float2(mu0, mu1);
            reinterpret_cast<float4*>(out + SIG_OFF)[(size_t)t * BB + gb] =
                make_float4(m00, m01, m01, m11);
            reinterpret_cast<float2*>(out + X_OFF)[(size_t)t * BB + gb] = make_float2(x0, x1);
            s_x[2 * b]     = x0;
            s_x[2 * b + 1] = x1;
        }
        __syncthreads();

        // ===== Phase E: gi += W_ih[:,2t]*x0 + W_ih[:,2t+1]*x1 (rank-2 update) =====
        if (t < TT - 1) {
            const int c0 = 2 * t;
            for (int idx = tid; idx < GG * 16; idx += NTH) {
                int jj = idx >> 4, bp = idx & 15;
                float w0 = g_WihT[c0 * GG + jj];
                float w1 = g_WihT[(c0 + 1) * GG + jj];
                float2 xb0 = make_float2(s_x[4 * bp],     s_x[4 * bp + 2]);
                float2 xb1 = make_float2(s_x[4 * bp + 1], s_x[4 * bp + 3]);
                float2 g = reinterpret_cast<float2*>(s_gi)[jj * 16 + bp];
                g = ffma2(xb0, make_float2(w0, w0), g);
                g = ffma2(xb1, make_float2(w1, w1), g);
                reinterpret_cast<float2*>(s_gi)[jj * 16 + bp] = g;
            }
        }
        __syncthreads();
    }
}

extern "C" void kernel_launch(void* const* d_in, const int* in_sizes, int n_in,
                              void* d_out, int out_size) {
    const float* stat   = (const float*)d_in[0];
    const float* init_v = (const float*)d_in[1];
    const float* init_p = (const float*)d_in[2];
    const float* z      = (const float*)d_in[3];
    const float* W_ih   = (const float*)d_in[4];
    const float* W_hh   = (const float*)d_in[5];
    const float* b_ih   = (const float*)d_in[6];
    const float* b_hh   = (const float*)d_in[7];
    const float* W1     = (const float*)d_in[8];
    const float* b1     = (const float*)d_in[9];
    const float* W2     = (const float*)d_in[10];
    const float* b2     = (const float*)d_in[11];
    float* out = (float*)d_out;

    transpose_weights<<<(GG * HH + 255) / 256, 256>>>(W_hh, W_ih);

    const size_t smem_bytes =
        (size_t)(GG * TB + HH * TB + SDD * TB * 2 + 6 * TB + TB * 2) * sizeof(float);
    cudaFuncSetAttribute(r2p2_kernel,
                         cudaFuncAttributeMaxDynamicSharedMemorySize,
                         (int)smem_bytes);
    r2p2_kernel<<<BB / TB, NTH, smem_bytes>>>(
        stat, init_v, init_p, z, b_ih, b_hh, W1, b1, W2, b2, out);
}

// round 3
// speedup vs baseline: 1.9781x; 1.0233x over previous
#include <cuda_runtime.h>
#include <math.h>

#define BB   131072
#define TT   30
#define HH   150
#define GG   450      // 3*H
#define SDD  50
#define TB   32       // batch tile per CTA
#define NTH  320      // 10 warps; 300 active in GEMM phase

// Device scratch for repacked weights (allowed: __device__ globals).
__device__ float4 g_Whh4[HH * HH];       // [k][j] -> (wr, wz, wn, 0), j<150
__device__ float2 g_Wih2[TT * GG];       // [t][j] -> (W_ih[j,2t], W_ih[j,2t+1])

// ---------- packed fp32x2 FMA (sm_103a) ----------
__device__ __forceinline__ float2 ffma2(float2 a, float2 b, float2 c) {
    float2 r;
    asm("{\n\t"
        ".reg .b64 ra, rb, rc, rd;\n\t"
        "mov.b64 ra, {%2, %3};\n\t"
        "mov.b64 rb, {%4, %5};\n\t"
        "mov.b64 rc, {%6, %7};\n\t"
        "fma.rn.f32x2 rd, ra, rb, rc;\n\t"
        "mov.b64 {%0, %1}, rd;\n\t"
        "}"
        : "=f"(r.x), "=f"(r.y)
        : "f"(a.x), "f"(a.y), "f"(b.x), "f"(b.y), "f"(c.x), "f"(c.y));
    return r;
}

// ---------- fast transcendentals (~2 ulp; tolerance is 1e-3) ----------
__device__ __forceinline__ float sigmf(float v) {
    return __fdividef(1.0f, 1.0f + __expf(-v));
}
__device__ __forceinline__ float tanh_fast(float v) {
    float x = fminf(fmaxf(v, -15.0f), 15.0f);
    float e = __expf(2.0f * x);
    return __fdividef(e - 1.0f, e + 1.0f);
}
__device__ __forceinline__ float softplusf(float v) {
    return fmaxf(v, 0.0f) + __logf(1.0f + __expf(-fabsf(v)));
}

// ---------- setup: repack W_hh and W_ih ----------
__global__ void repack_weights(const float* __restrict__ Whh,
                               const float* __restrict__ Wih) {
    int idx = blockIdx.x * blockDim.x + threadIdx.x;
    if (idx < HH * HH) {            // -> g_Whh4[k][j]
        int k = idx / HH, j = idx % HH;
        g_Whh4[idx] = make_float4(Whh[j * HH + k],
                                  Whh[(j + HH) * HH + k],
                                  Whh[(j + 2 * HH) * HH + k],
                                  0.0f);
    }
    if (idx < TT * GG) {            // -> g_Wih2[t][j]
        int t = idx / GG, j = idx % GG;
        g_Wih2[idx] = make_float2(Wih[j * (TT * 2) + 2 * t],
                                  Wih[j * (TT * 2) + 2 * t + 1]);
    }
}

// ---------- main fused recurrent kernel ----------
extern "C" __global__ void __launch_bounds__(NTH, 2)
r2p2_kernel(const float* __restrict__ stat,
            const float* __restrict__ init_v,
            const float* __restrict__ init_p,
            const float* __restrict__ zin,
            const float* __restrict__ b_ih,
            const float* __restrict__ b_hh,
            const float* __restrict__ W1,
            const float* __restrict__ b1,
            const float* __restrict__ W2,
            const float* __restrict__ b2,
            float* __restrict__ out) {
    extern __shared__ float smem[];
    float* s_gi = smem;                    // GG*TB   (layout [j][b])
    float* s_h  = s_gi + GG * TB;          // HH*TB   (layout [k][b])
    float* s_sp = s_h  + HH * TB;          // SDD*TB  (static proj + b1)
    float* s_o1 = s_sp + SDD * TB;         // SDD*TB
    float* s_o2 = s_o1 + SDD * TB;         // 6*TB
    float* s_x  = s_o2 + 6 * TB;           // TB*2

    const int tid = threadIdx.x;
    const int b0  = blockIdx.x * TB;
    const bool actA = (tid < 300);
    const int j    = tid >> 1;     // hidden unit 0..149
    const int half = tid & 1;      // batch-pair half: pairs [half*8, half*8+8)

    // ---- init: h = 0, gi = b_ih, s_proj = b1 + static @ W1_static^T ----
    for (int idx = tid; idx < HH * TB; idx += NTH) s_h[idx] = 0.0f;
    for (int idx = tid; idx < GG * TB; idx += NTH) s_gi[idx] = b_ih[idx >> 5];
    for (int idx = tid; idx < SDD * TB; idx += NTH) {
        int m = idx >> 5, b = idx & 31;
        float acc = b1[m];
        const float* wrow = W1 + m * (HH + SDD) + HH;
        const float* st   = stat + (size_t)(b0 + b) * SDD;
        #pragma unroll 5
        for (int d = 0; d < SDD; ++d) acc = fmaf(wrow[d], st[d], acc);
        s_sp[idx] = acc;
    }

    float xp0 = 0.f, xp1 = 0.f, dx0 = 0.f, dx1 = 0.f;
    if (tid < TB) {
        size_t g = (size_t)(b0 + tid) * 2;
        xp0 = init_p[g]; xp1 = init_p[g + 1];
        dx0 = init_v[g]; dx1 = init_v[g + 1];
    }
    __syncthreads();

    const size_t SIG_OFF = (size_t)2 * TT * BB;
    const size_t X_OFF   = (size_t)6 * TT * BB;

    for (int t = 0; t < TT; ++t) {
        // ===== Phase A: per-thread 3-gate rows (j, j+150, j+300) x 8 pairs =====
        float2 accR[8], accZ[8], accN[8];
        if (actA) {
            #pragma unroll
            for (int p = 0; p < 8; ++p) {
                accR[p] = make_float2(0.f, 0.f);
                accZ[p] = make_float2(0.f, 0.f);
                accN[p] = make_float2(0.f, 0.f);
            }
            const float4* wp  = g_Whh4 + j;
            const float4* hp4 = reinterpret_cast<const float4*>(s_h) + half * 4;
            #pragma unroll 2
            for (int k = 0; k < HH; ++k) {
                float4 w4 = __ldg(wp);
                wp += HH;
                float2 wr2 = make_float2(w4.x, w4.x);
                float2 wz2 = make_float2(w4.y, w4.y);
                float2 wn2 = make_float2(w4.z, w4.z);
                #pragma unroll
                for (int q = 0; q < 4; ++q) {
                    float4 hv = hp4[q];
                    float2 h0 = make_float2(hv.x, hv.y);
                    float2 h1 = make_float2(hv.z, hv.w);
                    accR[2*q]   = ffma2(h0, wr2, accR[2*q]);
                    accR[2*q+1] = ffma2(h1, wr2, accR[2*q+1]);
                    accZ[2*q]   = ffma2(h0, wz2, accZ[2*q]);
                    accZ[2*q+1] = ffma2(h1, wz2, accZ[2*q+1]);
                    accN[2*q]   = ffma2(h0, wn2, accN[2*q]);
                    accN[2*q+1] = ffma2(h1, wn2, accN[2*q+1]);
                }
                hp4 += 8;
            }
        }
        __syncthreads();   // all reads of old h complete

        // ===== Phase B: GRU gates in-register, write h_new =====
        if (actA) {
            float bhr = b_hh[j];
            float bhz = b_hh[j + HH];
            float bhn = b_hh[j + 2 * HH];
            const float2* gi2 = reinterpret_cast<const float2*>(s_gi);
            float2* h2 = reinterpret_cast<float2*>(s_h);
            #pragma unroll
            for (int p = 0; p < 8; ++p) {
                int pr = half * 8 + p;
                float2 vr = gi2[j * 16 + pr];
                float2 vz = gi2[(j + HH) * 16 + pr];
                float2 vn = gi2[(j + 2 * HH) * 16 + pr];
                float rx = sigmf(vr.x + accR[p].x + bhr);
                float ry = sigmf(vr.y + accR[p].y + bhr);
                float zx = sigmf(vz.x + accZ[p].x + bhz);
                float zy = sigmf(vz.y + accZ[p].y + bhz);
                float nx = tanh_fast(fmaf(rx, accN[p].x + bhn, vn.x));
                float ny = tanh_fast(fmaf(ry, accN[p].y + bhn, vn.y));
                float2 hold = h2[j * 16 + pr];
                float2 hnew;
                hnew.x = fmaf(zx, hold.x - nx, nx);
                hnew.y = fmaf(zy, hold.y - ny, ny);
                h2[j * 16 + pr] = hnew;
            }
        }
        __syncthreads();

        // ===== Phase C: o1 = softplus(h_new @ W1h^T + s_proj) =====
        for (int idx = tid; idx < SDD * 16; idx += NTH) {
            int m = idx >> 4, bp = idx & 15;
            float2 acc = make_float2(0.f, 0.f);
            const float* wrow = W1 + m * (HH + SDD);
            const float2* hcol = reinterpret_cast<const float2*>(s_h) + bp;
            #pragma unroll 5
            for (int k = 0; k < HH; ++k) {
                float w = wrow[k];
                acc = ffma2(hcol[k * 16], make_float2(w, w), acc);
            }
            float2 sp = reinterpret_cast<const float2*>(s_sp)[m * 16 + bp];
            s_o1[m * TB + 2 * bp]     = softplusf(acc.x + sp.x);
            s_o1[m * TB + 2 * bp + 1] = softplusf(acc.y + sp.y);
        }
        __syncthreads();

        // ===== Phase D1: o2 = softplus(o1 @ W2^T + b2), 192 threads =====
        if (tid < 192) {
            int m = tid >> 5, b = tid & 31;
            float acc = b2[m];
            const float* w = W2 + m * SDD;
            #pragma unroll 5
            for (int k = 0; k < SDD; ++k)
                acc = fmaf(w[k], s_o1[k * TB + b], acc);
            s_o2[m * TB + b] = softplusf(acc);
        }
        __syncthreads();

        // ===== Phase D2: expm 2x2, x update, outputs (one thread per b) =====
        if (tid < TB) {
            const int b = tid;
            const int gb = b0 + b;
            float o20 = s_o2[0 * TB + b];
            float o21 = s_o2[1 * TB + b];
            float aS = 2.0f * s_o2[2 * TB + b];
            float bS = s_o2[3 * TB + b] + s_o2[4 * TB + b];
            float cS = 2.0f * s_o2[5 * TB + b];
            float half_tr   = 0.5f * (aS + cS);
            float half_diff = 0.5f * (aS - cS);
            float disc = sqrtf(fmaf(half_diff, half_diff, bS * bS));
            float d = fmaxf(disc, 1e-12f);
            float ed  = __expf(d);
            float edi = __fdividef(1.0f, ed);
            float sinhc = __fdividef(0.5f * (ed - edi), d);
            float coshd = 0.5f * (ed + edi);      // cosh(disc); disc==d unless disc<1e-12 -> cosh≈1
            if (disc < 1e-12f) coshd = 1.0f;
            float scale = __expf(half_tr);
            float m00 = scale * fmaf(sinhc,  half_diff, coshd);
            float m11 = scale * fmaf(-sinhc, half_diff, coshd);
            float m01 = scale * (sinhc * bS);

            float mu0 = xp0 + dx0 + o20;
            float mu1 = xp1 + dx1 + o21;
            float2 zv = reinterpret_cast<const float2*>(zin)[(size_t)t * BB + gb];
            float x0 = fmaf(m00, zv.x, fmaf(m01, zv.y, mu0));
            float x1 = fmaf(m01, zv.x, fmaf(m11, zv.y, mu1));
            dx0 = x0 - xp0; dx1 = x1 - xp1;
            xp0 = x0;       xp1 = x1;

            reinterpret_cast<float2*>(out)[(size_t)t * BB + gb] = make_float2(mu0, mu1);
            reinterpret_cast<float4*>(out + SIG_OFF)[(size_t)t * BB + gb] =
                make_float4(m00, m01, m01, m11);
            reinterpret_cast<float2*>(out + X_OFF)[(size_t)t * BB + gb] = make_float2(x0, x1);
            s_x[2 * b]     = x0;
            s_x[2 * b + 1] = x1;
        }
        __syncthreads();

        // ===== Phase E: gi += W_ih[:,2t]*x0 + W_ih[:,2t+1]*x1 (rank-2 update) =====
        if (t < TT - 1) {
            const float2* wt = g_Wih2 + t * GG;
            for (int idx = tid; idx < GG * 16; idx += NTH) {
                int jj = idx >> 4, bp = idx & 15;
                float2 w = __ldg(wt + jj);
                float2 xb0 = make_float2(s_x[4 * bp],     s_x[4 * bp + 2]);
                float2 xb1 = make_float2(s_x[4 * bp + 1], s_x[4 * bp + 3]);
                float2 g = reinterpret_cast<float2*>(s_gi)[jj * 16 + bp];
                g = ffma2(xb0, make_float2(w.x, w.x), g);
                g = ffma2(xb1, make_float2(w.y, w.y), g);
                reinterpret_cast<float2*>(s_gi)[jj * 16 + bp] = g;
            }
        }
        __syncthreads();
    }
}

extern "C" void kernel_launch(void* const* d_in, const int* in_sizes, int n_in,
                              void* d_out, int out_size) {
    const float* stat   = (const float*)d_in[0];
    const float* init_v = (const float*)d_in[1];
    const float* init_p = (const float*)d_in[2];
    const float* z      = (const float*)d_in[3];
    const float* W_ih   = (const float*)d_in[4];
    const float* W_hh   = (const float*)d_in[5];
    const float* b_ih   = (const float*)d_in[6];
    const float* b_hh   = (const float*)d_in[7];
    const float* W1     = (const float*)d_in[8];
    const float* b1     = (const float*)d_in[9];
    const float* W2     = (const float*)d_in[10];
    const float* b2     = (const float*)d_in[11];
    float* out = (float*)d_out;

    repack_weights<<<(HH * HH + 255) / 256, 256>>>(W_hh, W_ih);

    const size_t smem_bytes =
        (size_t)(GG * TB + HH * TB + SDD * TB * 2 + 6 * TB + TB * 2) * sizeof(float);
    cudaFuncSetAttribute(r2p2_kernel,
                         cudaFuncAttributeMaxDynamicSharedMemorySize,
                         (int)smem_bytes);
    r2p2_kernel<<<BB / TB, NTH, smem_bytes>>>(
        stat, init_v, init_p, z, b_ih, b_hh, W1, b1, W2, b2, out);
}

// round 4
// speedup vs baseline: 2.3460x; 1.1859x over previous
#include <cuda_runtime.h>
#include <math.h>

#define BB   131072
#define TT   30
#define HH   150
#define GG   450      // 3*H
#define SDD  50
#define TB   32       // batch tile per CTA
#define NTH  320      // 10 warps; 300 active in GEMM phase

// Device scratch for repacked weights (allowed: __device__ globals).
__device__ float4 g_Whh4[HH * HH];       // [k][j] -> (wr, wz, wn, 0), j<150
__device__ float2 g_Wih2[TT * GG];       // [t][j] -> (W_ih[j,2t], W_ih[j,2t+1])
__device__ float  g_W1p[HH * 80];        // [k][g][8]: W1[(5g+i)][k], i<5 (pad 8)

// ---------- packed fp32x2 FMA (sm_103a) ----------
__device__ __forceinline__ float2 ffma2(float2 a, float2 b, float2 c) {
    float2 r;
    asm("{\n\t"
        ".reg .b64 ra, rb, rc, rd;\n\t"
        "mov.b64 ra, {%2, %3};\n\t"
        "mov.b64 rb, {%4, %5};\n\t"
        "mov.b64 rc, {%6, %7};\n\t"
        "fma.rn.f32x2 rd, ra, rb, rc;\n\t"
        "mov.b64 {%0, %1}, rd;\n\t"
        "}"
        : "=f"(r.x), "=f"(r.y)
        : "f"(a.x), "f"(a.y), "f"(b.x), "f"(b.y), "f"(c.x), "f"(c.y));
    return r;
}

// ---------- HW MUFU transcendentals ----------
__device__ __forceinline__ float tanh_hw(float x) {
    float y;
    asm("tanh.approx.f32 %0, %1;" : "=f"(y) : "f"(x));
    return y;
}
__device__ __forceinline__ float sigmf(float v) {
    return fmaf(0.5f, tanh_hw(0.5f * v), 0.5f);
}
__device__ __forceinline__ float softplusf(float v) {
    return fmaxf(v, 0.0f) + __logf(1.0f + __expf(-fabsf(v)));
}

// ---------- setup: repack weights ----------
__global__ void repack_weights(const float* __restrict__ Whh,
                               const float* __restrict__ Wih,
                               const float* __restrict__ W1) {
    int idx = blockIdx.x * blockDim.x + threadIdx.x;
    if (idx < HH * HH) {            // -> g_Whh4[k][j]
        int k = idx / HH, j = idx % HH;
        g_Whh4[idx] = make_float4(Whh[j * HH + k],
                                  Whh[(j + HH) * HH + k],
                                  Whh[(j + 2 * HH) * HH + k],
                                  0.0f);
    }
    if (idx < TT * GG) {            // -> g_Wih2[t][j]
        int t = idx / GG, j = idx % GG;
        g_Wih2[idx] = make_float2(Wih[j * (TT * 2) + 2 * t],
                                  Wih[j * (TT * 2) + 2 * t + 1]);
    }
    if (idx < HH * 80) {            // -> g_W1p[k][g][i], i<8 (5 used)
        int k = idx / 80, r = idx % 80;
        int g = r >> 3, i = r & 7;
        float v = 0.0f;
        if (i < 5) v = W1[(5 * g + i) * (HH + SDD) + k];
        g_W1p[idx] = v;
    }
}

// ---------- main fused recurrent kernel ----------
extern "C" __global__ void __launch_bounds__(NTH, 2)
r2p2_kernel(const float* __restrict__ stat,
            const float* __restrict__ init_v,
            const float* __restrict__ init_p,
            const float* __restrict__ zin,
            const float* __restrict__ b_ih,
            const float* __restrict__ b_hh,
            const float* __restrict__ W1,
            const float* __restrict__ b1,
            const float* __restrict__ W2,
            const float* __restrict__ b2,
            float* __restrict__ out) {
    extern __shared__ float smem[];
    float* s_gi = smem;                    // GG*TB   (layout [j][b])
    float* s_h  = s_gi + GG * TB;          // HH*TB   (layout [k][b])
    float* s_sp = s_h  + HH * TB;          // SDD*TB  (static proj + b1)
    float* s_o1 = s_sp + SDD * TB;         // SDD*TB
    float* s_o2 = s_o1 + SDD * TB;         // 6*TB
    float* s_x  = s_o2 + 6 * TB;           // TB*2

    const int tid = threadIdx.x;
    const int b0  = blockIdx.x * TB;
    const bool actA = (tid < 300);
    const int j    = tid >> 1;     // hidden unit 0..149
    const int half = tid & 1;      // batch-pair half: pairs [half*8, half*8+8)

    // Phase-C decomposition: tid = g*32 + bp*2 + kh
    const int c_g  = tid >> 5;          // m-group 0..9
    const int c_bp = (tid & 31) >> 1;   // batch pair 0..15
    const int c_kh = tid & 1;           // k half

    // ---- init: h = 0, gi = b_ih, s_proj = b1 + static @ W1_static^T ----
    for (int idx = tid; idx < HH * TB; idx += NTH) s_h[idx] = 0.0f;
    for (int idx = tid; idx < GG * TB; idx += NTH) s_gi[idx] = b_ih[idx >> 5];
    for (int idx = tid; idx < SDD * TB; idx += NTH) {
        int m = idx >> 5, b = idx & 31;
        float acc = b1[m];
        const float* wrow = W1 + m * (HH + SDD) + HH;
        const float* st   = stat + (size_t)(b0 + b) * SDD;
        #pragma unroll 5
        for (int d = 0; d < SDD; ++d) acc = fmaf(wrow[d], st[d], acc);
        s_sp[idx] = acc;
    }

    float xp0 = 0.f, xp1 = 0.f, dx0 = 0.f, dx1 = 0.f;
    if (tid < TB) {
        size_t g = (size_t)(b0 + tid) * 2;
        xp0 = init_p[g]; xp1 = init_p[g + 1];
        dx0 = init_v[g]; dx1 = init_v[g + 1];
    }
    __syncthreads();

    const size_t SIG_OFF = (size_t)2 * TT * BB;
    const size_t X_OFF   = (size_t)6 * TT * BB;

    for (int t = 0; t < TT; ++t) {
        // ===== Phase A: per-thread 3-gate rows (j, j+150, j+300) x 8 pairs =====
        float2 accR[8], accZ[8], accN[8];
        if (actA) {
            #pragma unroll
            for (int p = 0; p < 8; ++p) {
                accR[p] = make_float2(0.f, 0.f);
                accZ[p] = make_float2(0.f, 0.f);
                accN[p] = make_float2(0.f, 0.f);
            }
            const float4* wp  = g_Whh4 + j;
            const float4* hp4 = reinterpret_cast<const float4*>(s_h) + half * 4;
            #pragma unroll 2
            for (int k = 0; k < HH; ++k) {
                float4 w4 = __ldg(wp);
                wp += HH;
                float2 wr2 = make_float2(w4.x, w4.x);
                float2 wz2 = make_float2(w4.y, w4.y);
                float2 wn2 = make_float2(w4.z, w4.z);
                #pragma unroll
                for (int q = 0; q < 4; ++q) {
                    float4 hv = hp4[q];
                    float2 h0 = make_float2(hv.x, hv.y);
                    float2 h1 = make_float2(hv.z, hv.w);
                    accR[2*q]   = ffma2(h0, wr2, accR[2*q]);
                    accR[2*q+1] = ffma2(h1, wr2, accR[2*q+1]);
                    accZ[2*q]   = ffma2(h0, wz2, accZ[2*q]);
                    accZ[2*q+1] = ffma2(h1, wz2, accZ[2*q+1]);
                    accN[2*q]   = ffma2(h0, wn2, accN[2*q]);
                    accN[2*q+1] = ffma2(h1, wn2, accN[2*q+1]);
                }
                hp4 += 8;
            }
        }
        __syncthreads();   // all reads of old h complete

        // ===== Phase B: GRU gates in-register, write h_new (float4 over 2 pairs) =====
        if (actA) {
            float bhr = b_hh[j];
            float bhz = b_hh[j + HH];
            float bhn = b_hh[j + 2 * HH];
            const float4* gi4 = reinterpret_cast<const float4*>(s_gi);
            float4* h4 = reinterpret_cast<float4*>(s_h);
            #pragma unroll
            for (int q = 0; q < 4; ++q) {
                int fq = j * 8 + half * 4 + q;   // float4 slot
                float4 vr = gi4[(j) * 8 + half * 4 + q];
                float4 vz = gi4[(j + HH) * 8 + half * 4 + q];
                float4 vn = gi4[(j + 2 * HH) * 8 + half * 4 + q];
                float2 aR0 = accR[2*q],   aR1 = accR[2*q+1];
                float2 aZ0 = accZ[2*q],   aZ1 = accZ[2*q+1];
                float2 aN0 = accN[2*q],   aN1 = accN[2*q+1];
                float r0 = sigmf(vr.x + aR0.x + bhr);
                float r1 = sigmf(vr.y + aR0.y + bhr);
                float r2 = sigmf(vr.z + aR1.x + bhr);
                float r3 = sigmf(vr.w + aR1.y + bhr);
                float z0 = sigmf(vz.x + aZ0.x + bhz);
                float z1 = sigmf(vz.y + aZ0.y + bhz);
                float z2 = sigmf(vz.z + aZ1.x + bhz);
                float z3 = sigmf(vz.w + aZ1.y + bhz);
                float n0 = tanh_hw(fmaf(r0, aN0.x + bhn, vn.x));
                float n1 = tanh_hw(fmaf(r1, aN0.y + bhn, vn.y));
                float n2 = tanh_hw(fmaf(r2, aN1.x + bhn, vn.z));
                float n3 = tanh_hw(fmaf(r3, aN1.y + bhn, vn.w));
                float4 hold = h4[fq];
                float4 hnew;
                hnew.x = fmaf(z0, hold.x - n0, n0);
                hnew.y = fmaf(z1, hold.y - n1, n1);
                hnew.z = fmaf(z2, hold.z - n2, n2);
                hnew.w = fmaf(z3, hold.w - n3, n3);
                h4[fq] = hnew;
            }
        }
        __syncthreads();

        // ===== Phase C: o1 = softplus(h_new @ W1h^T + s_proj) =====
        // thread = (m-group g of 5, batch pair bp, k-half kh); shuffle-reduce kh.
        {
            float2 acc0 = make_float2(0.f, 0.f);
            float2 acc1 = acc0, acc2 = acc0, acc3 = acc0, acc4 = acc0;
            const float2* hcol = reinterpret_cast<const float2*>(s_h)
                                 + c_kh * 75 * 16 + c_bp;
            const float* wb = g_W1p + c_kh * 75 * 80 + c_g * 8;
            #pragma unroll 3
            for (int kk = 0; kk < 75; ++kk) {
                float2 hv = hcol[kk * 16];
                float4 w4 = __ldg(reinterpret_cast<const float4*>(wb));
                float  w5 = __ldg(wb + 4);
                wb += 80;
                acc0 = ffma2(hv, make_float2(w4.x, w4.x), acc0);
                acc1 = ffma2(hv, make_float2(w4.y, w4.y), acc1);
                acc2 = ffma2(hv, make_float2(w4.z, w4.z), acc2);
                acc3 = ffma2(hv, make_float2(w4.w, w4.w), acc3);
                acc4 = ffma2(hv, make_float2(w5,  w5 ), acc4);
            }
            // reduce across kh (partner lane = lane^1)
            acc0.x += __shfl_xor_sync(0xFFFFFFFF, acc0.x, 1);
            acc0.y += __shfl_xor_sync(0xFFFFFFFF, acc0.y, 1);
            acc1.x += __shfl_xor_sync(0xFFFFFFFF, acc1.x, 1);
            acc1.y += __shfl_xor_sync(0xFFFFFFFF, acc1.y, 1);
            acc2.x += __shfl_xor_sync(0xFFFFFFFF, acc2.x, 1);
            acc2.y += __shfl_xor_sync(0xFFFFFFFF, acc2.y, 1);
            acc3.x += __shfl_xor_sync(0xFFFFFFFF, acc3.x, 1);
            acc3.y += __shfl_xor_sync(0xFFFFFFFF, acc3.y, 1);
            acc4.x += __shfl_xor_sync(0xFFFFFFFF, acc4.x, 1);
            acc4.y += __shfl_xor_sync(0xFFFFFFFF, acc4.y, 1);
            if (c_kh == 0) {
                float2 accs[5] = {acc0, acc1, acc2, acc3, acc4};
                #pragma unroll
                for (int i = 0; i < 5; ++i) {
                    int m = 5 * c_g + i;
                    float2 sp = reinterpret_cast<const float2*>(s_sp)[m * 16 + c_bp];
                    s_o1[m * TB + 2 * c_bp]     = softplusf(accs[i].x + sp.x);
                    s_o1[m * TB + 2 * c_bp + 1] = softplusf(accs[i].y + sp.y);
                }
            }
        }
        __syncthreads();

        // ===== Phase D1: o2 = softplus(o1 @ W2^T + b2), 192 threads =====
        if (tid < 192) {
            int m = tid >> 5, b = tid & 31;
            float acc = b2[m];
            const float* w = W2 + m * SDD;
            #pragma unroll 5
            for (int k = 0; k < SDD; ++k)
                acc = fmaf(w[k], s_o1[k * TB + b], acc);
            s_o2[m * TB + b] = softplusf(acc);
        }
        __syncthreads();

        // ===== Phase D2: expm 2x2, x update, outputs (one thread per b) =====
        if (tid < TB) {
            const int b = tid;
            const int gb = b0 + b;
            float o20 = s_o2[0 * TB + b];
            float o21 = s_o2[1 * TB + b];
            float aS = 2.0f * s_o2[2 * TB + b];
            float bS = s_o2[3 * TB + b] + s_o2[4 * TB + b];
            float cS = 2.0f * s_o2[5 * TB + b];
            float half_tr   = 0.5f * (aS + cS);
            float half_diff = 0.5f * (aS - cS);
            float disc = sqrtf(fmaf(half_diff, half_diff, bS * bS));
            float d = fmaxf(disc, 1e-12f);
            float ed  = __expf(d);
            float edi = __fdividef(1.0f, ed);
            float sinhc = __fdividef(0.5f * (ed - edi), d);
            float coshd = 0.5f * (ed + edi);
            if (disc < 1e-12f) coshd = 1.0f;
            float scale = __expf(half_tr);
            float m00 = scale * fmaf(sinhc,  half_diff, coshd);
            float m11 = scale * fmaf(-sinhc, half_diff, coshd);
            float m01 = scale * (sinhc * bS);

            float mu0 = xp0 + dx0 + o20;
            float mu1 = xp1 + dx1 + o21;
            float2 zv = reinterpret_cast<const float2*>(zin)[(size_t)t * BB + gb];
            float x0 = fmaf(m00, zv.x, fmaf(m01, zv.y, mu0));
            float x1 = fmaf(m01, zv.x, fmaf(m11, zv.y, mu1));
            dx0 = x0 - xp0; dx1 = x1 - xp1;
            xp0 = x0;       xp1 = x1;

            reinterpret_cast<float2*>(out)[(size_t)t * BB + gb] = make_float2(mu0, mu1);
            reinterpret_cast<float4*>(out + SIG_OFF)[(size_t)t * BB + gb] =
                make_float4(m00, m01, m01, m11);
            reinterpret_cast<float2*>(out + X_OFF)[(size_t)t * BB + gb] = make_float2(x0, x1);
            s_x[2 * b]     = x0;
            s_x[2 * b + 1] = x1;
        }
        __syncthreads();

        // ===== Phase E: gi += W_ih[:,2t]*x0 + W_ih[:,2t+1]*x1 (rank-2 update) =====
        if (t < TT - 1) {
            const float2* wt = g_Wih2 + t * GG;
            for (int idx = tid; idx < GG * 16; idx += NTH) {
                int jj = idx >> 4, bp = idx & 15;
                float2 w = __ldg(wt + jj);
                float2 xb0 = make_float2(s_x[4 * bp],     s_x[4 * bp + 2]);
                float2 xb1 = make_float2(s_x[4 * bp + 1], s_x[4 * bp + 3]);
                float2 g = reinterpret_cast<float2*>(s_gi)[jj * 16 + bp];
                g = ffma2(xb0, make_float2(w.x, w.x), g);
                g = ffma2(xb1, make_float2(w.y, w.y), g);
                reinterpret_cast<float2*>(s_gi)[jj * 16 + bp] = g;
            }
        }
        __syncthreads();
    }
}

extern "C" void kernel_launch(void* const* d_in, const int* in_sizes, int n_in,
                              void* d_out, int out_size) {
    const float* stat   = (const float*)d_in[0];
    const float* init_v = (const float*)d_in[1];
    const float* init_p = (const float*)d_in[2];
    const float* z      = (const float*)d_in[3];
    const float* W_ih   = (const float*)d_in[4];
    const float* W_hh   = (const float*)d_in[5];
    const float* b_ih   = (const float*)d_in[6];
    const float* b_hh   = (const float*)d_in[7];
    const float* W1     = (const float*)d_in[8];
    const float* b1     = (const float*)d_in[9];
    const float* W2     = (const float*)d_in[10];
    const float* b2     = (const float*)d_in[11];
    float* out = (float*)d_out;

    repack_weights<<<(HH * HH + 255) / 256, 256>>>(W_hh, W_ih, W1);

    const size_t smem_bytes =
        (size_t)(GG * TB + HH * TB + SDD * TB * 2 + 6 * TB + TB * 2) * sizeof(float);
    cudaFuncSetAttribute(r2p2_kernel,
                         cudaFuncAttributeMaxDynamicSharedMemorySize,
                         (int)smem_bytes);
    r2p2_kernel<<<BB / TB, NTH, smem_bytes>>>(
        stat, init_v, init_p, z, b_ih, b_hh, W1, b1, W2, b2, out);
}